// round 10
// baseline (speedup 1.0000x reference)
#include <cuda_runtime.h>
#include <cstdint>

#define HW 65536
#define NPIX 131072   // B * H * W = 2*256*256
#define OUT_PRIOR 393216
#define OUT_Y 1310720

typedef unsigned long long ull;

__device__ __forceinline__ ull pack2(float lo, float hi) {
    ull r; asm("mov.b64 %0, {%1, %2};" : "=l"(r) : "f"(lo), "f"(hi)); return r;
}
__device__ __forceinline__ void unpack2(ull v, float& lo, float& hi) {
    asm("mov.b64 {%0, %1}, %2;" : "=f"(lo), "=f"(hi) : "l"(v));
}
__device__ __forceinline__ void ffma2(ull& d, ull a, ull b) {
    asm("fma.rn.f32x2 %0, %1, %2, %0;" : "+l"(d) : "l"(a), "l"(b));
}
__device__ __forceinline__ ull addf2(ull a, ull b) {
    ull r; asm("add.rn.f32x2 %0, %1, %2;" : "=l"(r) : "l"(a), "l"(b)); return r;
}

// ---------------- device scratch (static: no allocs allowed) ----------------
__device__ float g_h1[2u*32u*7u*HW];
__device__ float g_h2[2u*32u*7u*HW];
__device__ float g_guide[2u*7u*HW];
__device__ float g_domk[4*27];
__device__ float g_wt[4u*NPIX*27u];
__device__ float g_xc[2u*3u*HW];
__device__ float g_ypre[NPIX];
__device__ float g_r[NPIX];

// ---------------- init: xc = x[:, :, 2:5] (raw, no relu) ----------------
__global__ void init_xc_kernel(const float* __restrict__ x) {
    int t = blockIdx.x * 256 + threadIdx.x;           // 0 .. 393215
    int b = t / (3 * HW);
    int rem = t - b * 3 * HW;
    int s = rem / HW;
    int hw = rem - s * HW;
    g_xc[t] = x[(b * 7 + 2 + s) * HW + hw];
}

// ---------------- conv1: 1 -> 32, 3x3x3 SAME, relu ----------------
__global__ __launch_bounds__(256) void conv1_kernel(
    const float* __restrict__ x, const float* __restrict__ w, const float* __restrict__ bias)
{
    __shared__ float ws[27 * 32];   // [tap][oc]
    __shared__ float bs[32];
    int tid = threadIdx.x;
    for (int t = tid; t < 864; t += 256) {
        int tap = t >> 5, oc = t & 31;
        ws[t] = w[oc * 27 + tap];
    }
    if (tid < 32) bs[tid] = bias[tid];
    __syncthreads();

    int hw = blockIdx.x * 256 + tid;
    int h = hw >> 8, wq = hw & 255;
    int d = blockIdx.y, b = blockIdx.z;

    const float* xp = x + (size_t)(b * 7 + d) * HW + hw;
    bool h0 = h > 0, h2 = h < 255, w0 = wq > 0, w2 = wq < 255;

    float v[27];
#pragma unroll
    for (int kd = 0; kd < 3; ++kd) {
        int dd = d + kd - 1;
        bool dok = (unsigned)dd < 7u;
        const float* ipd = xp + (kd - 1) * HW;
#pragma unroll
        for (int kh = 0; kh < 3; ++kh) {
            bool hok = (kh == 0) ? h0 : (kh == 2 ? h2 : true);
            const float* iph = ipd + (kh - 1) * 256;
#pragma unroll
            for (int kw = 0; kw < 3; ++kw) {
                bool wok = (kw == 0) ? w0 : (kw == 2 ? w2 : true);
                v[kd * 9 + kh * 3 + kw] = (dok && hok && wok) ? iph[kw - 1] : 0.f;
            }
        }
    }

    float acc[32];
#pragma unroll
    for (int oc = 0; oc < 32; ++oc) acc[oc] = bs[oc];

    const float4* wp = (const float4*)ws;
#pragma unroll
    for (int tap = 0; tap < 27; ++tap) {
        float xv = v[tap];
#pragma unroll
        for (int q = 0; q < 8; ++q) {
            float4 ww = wp[tap * 8 + q];
            acc[q * 4 + 0] += xv * ww.x;
            acc[q * 4 + 1] += xv * ww.y;
            acc[q * 4 + 2] += xv * ww.z;
            acc[q * 4 + 3] += xv * ww.w;
        }
    }

    float* ob = g_h1 + (size_t)b * 32 * 7 * HW + (size_t)d * HW + hw;
#pragma unroll
    for (int oc = 0; oc < 32; ++oc)
        ob[(size_t)oc * 7 * HW] = fmaxf(acc[oc], 0.f);
}

// ---------------- conv32 v7: f32x2 over oc-pairs, 8 oc/block, 4 px/thread ----
// dir == 0 : g_h1 -> g_h2 ; dir == 1 : g_h2 -> g_h1
// grid: (64 tiles, 7 d, b*4 + ocg); tile 16h x 64w
// thread (th, tw): pixels (ty+th, tx+tw), (ty+th+8, tx+tw), and +32 cols.
// accumulators a[px*4+j] hold oc pair (2j, 2j+1).
#define T4ROW 66
#define T4SLICE 1188           // 18*66
#define T4ELEMS 3564           // 3*18*66
#define CONV7SM (27648 + 64 + 2 * T4ELEMS * 4)   // 56,224 B
__global__ __launch_bounds__(256, 2) void conv32_v7(
    int dir, const float* __restrict__ w, const float* __restrict__ bias)
{
    extern __shared__ char smemraw[];
    float* wsm = (float*)smemraw;               // 6912 floats [(ic*27+tap)*8 + o]
    ull*   bs2 = (ull*)(smemraw + 27648);       // 4 oc-pair biases
    float* tls = (float*)(smemraw + 27712);     // 2 * 3564 floats

    int tid = threadIdx.x;
    int zb = blockIdx.z;
    int b = zb >> 2, ocg = zb & 3;

    for (int t = tid; t < 6912; t += 256) {
        int o = t & 7;
        int rest = t >> 3;                      // = ic*27 + tap
        int ic = rest / 27, tap = rest - ic * 27;
        wsm[t] = w[((ocg * 8 + o) * 32 + ic) * 27 + tap];
    }
    if (tid < 4) bs2[tid] = pack2(bias[ocg * 8 + 2 * tid], bias[ocg * 8 + 2 * tid + 1]);

    int tile = blockIdx.x;                      // 0..63
    int tx = (tile & 3) << 6;                   // w origin (0,64,128,192)
    int ty = (tile >> 2) << 4;                  // h origin (0..240)
    int d = blockIdx.y;
    int tw = tid & 31, th = tid >> 5;

    const float* in = dir ? g_h2 : g_h1;
    float* out = dir ? g_h1 : g_h2;
    const float* inb = in + (size_t)b * 32 * 7 * HW;

    // preload ic = 0 into buffer 0
    {
        const float* ip = inb;
#pragma unroll
        for (int k = 0; k < 14; ++k) {
            int idx = tid + (k << 8);
            if (idx < T4ELEMS) {
                int dd = (idx >= T4SLICE) + (idx >= 2 * T4SLICE);
                int r  = idx - dd * T4SLICE;
                int hh = r / T4ROW;
                int ww = r - hh * T4ROW;
                int gd = d + dd - 1, gh = ty + hh - 1, gw = tx + ww - 1;
                float v = 0.f;
                if ((unsigned)gd < 7u && (unsigned)gh < 256u && (unsigned)gw < 256u)
                    v = ip[(size_t)gd * HW + gh * 256 + gw];
                tls[idx] = v;
            }
        }
    }

    ull a[16];   // a[px*4+j]: px in {r0c0, r1c0, r0c1, r1c1}, j = oc pair
#pragma unroll
    for (int o = 0; o < 16; ++o) a[o] = 0ull;

    __syncthreads();   // weights + first tile ready

    for (int ic = 0; ic < 32; ++ic) {
        const float* cur = tls + (ic & 1) * T4ELEMS;

        // stage next input tile in registers (hidden behind compute)
        float stage[14];
        if (ic < 31) {
            const float* ip = inb + (size_t)(ic + 1) * 7 * HW;
#pragma unroll
            for (int k = 0; k < 14; ++k) {
                int idx = tid + (k << 8);
                float v = 0.f;
                if (idx < T4ELEMS) {
                    int dd = (idx >= T4SLICE) + (idx >= 2 * T4SLICE);
                    int r  = idx - dd * T4SLICE;
                    int hh = r / T4ROW;
                    int ww = r - hh * T4ROW;
                    int gd = d + dd - 1, gh = ty + hh - 1, gw = tx + ww - 1;
                    if ((unsigned)gd < 7u && (unsigned)gh < 256u && (unsigned)gw < 256u)
                        v = ip[(size_t)gd * HW + gh * 256 + gw];
                }
                stage[k] = v;
            }
        }

        const float* wp = wsm + ic * 216;     // 27 taps * 8 oc
#pragma unroll
        for (int kd = 0; kd < 3; ++kd) {
#pragma unroll
            for (int kh = 0; kh < 3; ++kh) {
                const float* r0 = cur + kd * T4SLICE + (th + kh) * T4ROW + tw;
                const float* r1 = r0 + 8 * T4ROW;
#pragma unroll
                for (int kw = 0; kw < 3; ++kw) {
                    float v0 = r0[kw], v1 = r1[kw];
                    float v2 = r0[kw + 32], v3 = r1[kw + 32];
                    ull d0 = pack2(v0, v0), d1 = pack2(v1, v1);
                    ull d2 = pack2(v2, v2), d3 = pack2(v3, v3);
                    const ulonglong2* w2p =
                        (const ulonglong2*)(wp + ((kd * 9 + kh * 3 + kw) << 3));
                    ulonglong2 wA = w2p[0];   // (oc0,oc1) (oc2,oc3)
                    ulonglong2 wB = w2p[1];   // (oc4,oc5) (oc6,oc7)
                    ffma2(a[0],  d0, wA.x); ffma2(a[1],  d0, wA.y);
                    ffma2(a[2],  d0, wB.x); ffma2(a[3],  d0, wB.y);
                    ffma2(a[4],  d1, wA.x); ffma2(a[5],  d1, wA.y);
                    ffma2(a[6],  d1, wB.x); ffma2(a[7],  d1, wB.y);
                    ffma2(a[8],  d2, wA.x); ffma2(a[9],  d2, wA.y);
                    ffma2(a[10], d2, wB.x); ffma2(a[11], d2, wB.y);
                    ffma2(a[12], d3, wA.x); ffma2(a[13], d3, wA.y);
                    ffma2(a[14], d3, wB.x); ffma2(a[15], d3, wB.y);
                }
            }
        }

        if (ic < 31) {
            float* nxt = tls + ((ic + 1) & 1) * T4ELEMS;
#pragma unroll
            for (int k = 0; k < 14; ++k) {
                int idx = tid + (k << 8);
                if (idx < T4ELEMS) nxt[idx] = stage[k];
            }
            __syncthreads();
        }
    }

    size_t ob = (size_t)b * 32 * 7 * HW + (size_t)d * HW + (size_t)(ty + th) * 256 + tx + tw;
    size_t pxoff[4] = { 0, 8 * 256, 32, 8 * 256 + 32 };
#pragma unroll
    for (int px = 0; px < 4; ++px) {
#pragma unroll
        for (int j = 0; j < 4; ++j) {
            float lo, hi;
            unpack2(addf2(a[px * 4 + j], bs2[j]), lo, hi);
            size_t pp = ob + pxoff[px] + (size_t)(ocg * 8 + 2 * j) * 7 * HW;
            out[pp] = fmaxf(lo, 0.f);
            out[pp + 7 * HW] = fmaxf(hi, 0.f);
        }
    }
}

// ---------------- conv4 v4: 32 -> 1 SAME + x, double-buffered pipeline ----
#define TILE_ROW 34
#define TILE_SLICE 612
#define TILE_ELEMS 1836
__global__ __launch_bounds__(256) void conv4_v4(
    const float* __restrict__ x, const float* __restrict__ w,
    const float* __restrict__ bias, float* __restrict__ out_prior)
{
    __shared__ float ws[864];               // [ic*27+tap]
    __shared__ float tls[2 * TILE_ELEMS];
    int tid = threadIdx.x;
    for (int t = tid; t < 864; t += 256) ws[t] = w[t];

    int tileId = blockIdx.x;
    int tx = (tileId & 7) << 5;
    int ty = (tileId >> 3) << 4;
    int d = blockIdx.y, b = blockIdx.z;
    int tw = tid & 31, th = tid >> 5;

    const float* inb = g_h1 + (size_t)b * 32 * 7 * HW;

    // preload ic = 0
    {
        const float* ip = inb;
#pragma unroll
        for (int k = 0; k < 8; ++k) {
            int idx = tid + (k << 8);
            if (idx < TILE_ELEMS) {
                int dd = idx / TILE_SLICE;
                int r  = idx - dd * TILE_SLICE;
                int hh = r / TILE_ROW;
                int ww = r - hh * TILE_ROW;
                int gd = d + dd - 1, gh = ty + hh - 1, gw = tx + ww - 1;
                float v = 0.f;
                if ((unsigned)gd < 7u && (unsigned)gh < 256u && (unsigned)gw < 256u)
                    v = ip[(size_t)gd * HW + gh * 256 + gw];
                tls[idx] = v;
            }
        }
    }

    float a0 = 0.f, a1 = 0.f;
    __syncthreads();

    for (int ic = 0; ic < 32; ++ic) {
        const float* cur = tls + (ic & 1) * TILE_ELEMS;

        float stage[8];
        if (ic < 31) {
            const float* ip = inb + (size_t)(ic + 1) * 7 * HW;
#pragma unroll
            for (int k = 0; k < 8; ++k) {
                int idx = tid + (k << 8);
                float v = 0.f;
                if (idx < TILE_ELEMS) {
                    int dd = idx / TILE_SLICE;
                    int r  = idx - dd * TILE_SLICE;
                    int hh = r / TILE_ROW;
                    int ww = r - hh * TILE_ROW;
                    int gd = d + dd - 1, gh = ty + hh - 1, gw = tx + ww - 1;
                    if ((unsigned)gd < 7u && (unsigned)gh < 256u && (unsigned)gw < 256u)
                        v = ip[(size_t)gd * HW + gh * 256 + gw];
                }
                stage[k] = v;
            }
        }

        const float* wp = ws + ic * 27;
#pragma unroll
        for (int kd = 0; kd < 3; ++kd) {
#pragma unroll
            for (int kh = 0; kh < 3; ++kh) {
                const float* trow = cur + kd * TILE_SLICE + (th + kh) * TILE_ROW + tw;
#pragma unroll
                for (int kw = 0; kw < 3; ++kw) {
                    float wv = wp[kd * 9 + kh * 3 + kw];
                    a0 += trow[kw] * wv;
                    a1 += trow[kw + 8 * TILE_ROW] * wv;
                }
            }
        }

        if (ic < 31) {
            float* nxt = tls + ((ic + 1) & 1) * TILE_ELEMS;
#pragma unroll
            for (int k = 0; k < 8; ++k) {
                int idx = tid + (k << 8);
                if (idx < TILE_ELEMS) nxt[idx] = stage[k];
            }
            __syncthreads();
        }
    }

    float bv = bias[0];
    size_t oi0 = (size_t)(b * 7 + d) * HW + (size_t)(ty + th) * 256 + tx + tw;
    size_t oi1 = oi0 + 8 * 256;
    float g0 = a0 + bv + x[oi0];
    float g1 = a1 + bv + x[oi1];
    g_guide[oi0] = g0; g_guide[oi1] = g1;
    out_prior[oi0] = g0; out_prior[oi1] = g1;
}

// ---------------- domain kernel: 4 blocks (one per bilateral block) ----------------
__global__ void domain_kernel(
    const float* __restrict__ spat,
    const float* __restrict__ dw1, const float* __restrict__ db1,
    const float* __restrict__ dw2, const float* __restrict__ db2)
{
    int i = blockIdx.x;
    int tid = threadIdx.x;
    __shared__ float sp[343], hid[1000], w1s[216], w2s[216];
    for (int t = tid; t < 343; t += 256) sp[t] = spat[t];
    for (int t = tid; t < 216; t += 256) { w1s[t] = dw1[i * 216 + t]; w2s[t] = dw2[i * 216 + t]; }
    __syncthreads();

    for (int idx = tid; idx < 1000; idx += 256) {
        int m = idx / 125, p = idx % 125;
        int z = p / 25, y = (p / 5) % 5, xx = p % 5;
        float a = db1[i * 8 + m];
#pragma unroll
        for (int kd = 0; kd < 3; ++kd)
#pragma unroll
            for (int kh = 0; kh < 3; ++kh)
#pragma unroll
                for (int kw = 0; kw < 3; ++kw)
                    a += sp[(z + kd) * 49 + (y + kh) * 7 + (xx + kw)] * w1s[m * 27 + kd * 9 + kh * 3 + kw];
        hid[idx] = fmaxf(a, 0.f);
    }
    __syncthreads();

    if (tid < 27) {
        int z = tid / 9, y = (tid / 3) % 3, xx = tid % 3;
        float a = db2[i];
#pragma unroll
        for (int m = 0; m < 8; ++m)
#pragma unroll
            for (int kd = 0; kd < 3; ++kd)
#pragma unroll
                for (int kh = 0; kh < 3; ++kh)
#pragma unroll
                    for (int kw = 0; kw < 3; ++kw)
                        a += hid[m * 125 + (z + kd) * 25 + (y + kh) * 5 + (xx + kw)] *
                             w2s[m * 27 + kd * 9 + kh * 3 + kw];
        g_domk[i * 27 + tid] = fmaxf(a, 0.f);
    }
}

// ---------------- range kernel v4: warp/pixel, tap-outer f32x2 layer1 ----
__global__ __launch_bounds__(256) void rangek_kernel(
    const float* __restrict__ rw1, const float* __restrict__ rb1,
    const float* __restrict__ rw2, const float* __restrict__ rb2)
{
    __shared__ float gp8[8][344];
    __shared__ float hid8[8][1008];
    __shared__ __align__(16) float w1s[216];      // [tap*8 + m]
    __shared__ float w2s[216];                    // [m*27 + tap]

    int tid = threadIdx.x;
    int wid = tid >> 5, lane = tid & 31;
    int pix = blockIdx.x * 8 + wid;
    int b = pix >> 16;
    int hw = pix & 65535;
    int h = hw >> 8, wq = hw & 255;

    const float* gb = g_guide + (size_t)b * 7 * HW;
    float center = gb[3 * HW + hw];

    for (int idx = lane; idx < 343; idx += 32) {
        int d = idx / 49, rr = idx % 49;
        int ii = rr / 7, jj = rr % 7;
        int hh = h - 3 + ii, ww = wq - 3 + jj;
        float v = 0.f;
        if ((unsigned)hh < 256u && (unsigned)ww < 256u) v = gb[d * HW + hh * 256 + ww];
        gp8[wid][idx] = fabsf(v - center);
    }

    // per-rep position offsets (fixed across i)
    int off[4];
#pragma unroll
    for (int rep = 0; rep < 4; ++rep) {
        int p = lane + (rep << 5);
        int pp = p < 125 ? p : 124;
        int z = pp / 25, y = (pp / 5) % 5, xx = pp % 5;
        off[rep] = z * 49 + y * 7 + xx;
    }

    for (int i = 0; i < 4; ++i) {
        __syncthreads();
        for (int t = tid; t < 216; t += 256) {
            int m = t / 27, tap = t % 27;
            w1s[tap * 8 + m] = rw1[i * 216 + t];
            w2s[t] = rw2[i * 216 + t];
        }
        __syncthreads();

        const float* gp = gp8[wid];
        ull acc[16];   // [rep][mpair j] = (m=2j, 2j+1)
#pragma unroll
        for (int j = 0; j < 4; ++j) {
            ull bp = pack2(rb1[i * 8 + 2 * j], rb1[i * 8 + 2 * j + 1]);
            acc[j] = bp; acc[4 + j] = bp; acc[8 + j] = bp; acc[12 + j] = bp;
        }

#pragma unroll
        for (int kd = 0; kd < 3; ++kd)
#pragma unroll
            for (int kh = 0; kh < 3; ++kh)
#pragma unroll
                for (int kw = 0; kw < 3; ++kw) {
                    int tap = kd * 9 + kh * 3 + kw;
                    const ulonglong2* w2p = (const ulonglong2*)(w1s + tap * 8);
                    ulonglong2 wA = w2p[0];   // (m0,m1) (m2,m3)
                    ulonglong2 wB = w2p[1];   // (m4,m5) (m6,m7)
                    int to = kd * 49 + kh * 7 + kw;
#pragma unroll
                    for (int rep = 0; rep < 4; ++rep) {
                        float g = gp[off[rep] + to];
                        ull gd = pack2(g, g);
                        ull* ac = acc + rep * 4;
                        ffma2(ac[0], gd, wA.x); ffma2(ac[1], gd, wA.y);
                        ffma2(ac[2], gd, wB.x); ffma2(ac[3], gd, wB.y);
                    }
                }

#pragma unroll
        for (int rep = 0; rep < 4; ++rep) {
            int p = lane + (rep << 5);
            if (p < 125) {
#pragma unroll
                for (int j = 0; j < 4; ++j) {
                    float lo, hi;
                    unpack2(acc[rep * 4 + j], lo, hi);
                    hid8[wid][(2 * j) * 125 + p]     = fmaxf(lo, 0.f);
                    hid8[wid][(2 * j + 1) * 125 + p] = fmaxf(hi, 0.f);
                }
            }
        }
        __syncwarp();

        float wt = 0.f;
        if (lane < 27) {
            int z = lane / 9, y = (lane / 3) % 3, xx = lane % 3;
            float a = rb2[i];
            const float* hd = hid8[wid];
#pragma unroll
            for (int m = 0; m < 8; ++m)
#pragma unroll
                for (int kd = 0; kd < 3; ++kd)
#pragma unroll
                    for (int kh = 0; kh < 3; ++kh)
#pragma unroll
                        for (int kw = 0; kw < 3; ++kw)
                            a += hd[m * 125 + (z + kd) * 25 + (y + kh) * 5 + (xx + kw)] *
                                 w2s[m * 27 + kd * 9 + kh * 3 + kw];
            a = fmaxf(a, 0.f);
            wt = g_domk[i * 27 + lane] * a;
        }
        float s = wt;
#pragma unroll
        for (int off2 = 16; off2; off2 >>= 1) s += __shfl_down_sync(0xffffffffu, s, off2);
        s = __shfl_sync(0xffffffffu, s, 0);
        if (lane < 27)
            g_wt[((size_t)i * NPIX + pix) * 27 + lane] = wt / (s + 1e-6f);
        __syncwarp();
    }
}

// ---------------- bilateral gather per block i ----------------
__global__ void bilateral_kernel(int i, const float* __restrict__ x) {
    int pix = blockIdx.x * 256 + threadIdx.x;
    int b = pix >> 16;
    int hw = pix & 65535;
    int h = hw >> 8, wq = hw & 255;

    const float* wp = g_wt + ((size_t)i * NPIX + pix) * 27;
    const float* xcb = g_xc + (size_t)b * 3 * HW;

    float y = 0.f;
#pragma unroll
    for (int dz = 0; dz < 3; ++dz) {
#pragma unroll
        for (int dy = 0; dy < 3; ++dy) {
            int hh = h + dy - 1;
            bool hok = (unsigned)hh < 256u;
#pragma unroll
            for (int dx = 0; dx < 3; ++dx) {
                int ww = wq + dx - 1;
                bool wok = (unsigned)ww < 256u;
                float v = (hok && wok) ? xcb[dz * HW + hh * 256 + ww] : 0.f;
                y += wp[dz * 9 + dy * 3 + dx] * v;
            }
        }
    }
    y = fmaxf(y, 0.f);
    float ref = x[(b * 7 + 3) * HW + hw];
    g_ypre[pix] = y;
    g_r[pix] = y - ref;
}

// ---------------- alfa residual kernel per block i ----------------
__global__ void alfa_kernel(int i, const float* __restrict__ x,
                            const float* __restrict__ aw, const float* __restrict__ ab,
                            float* __restrict__ out)
{
    int pix = blockIdx.x * 256 + threadIdx.x;
    int b = pix >> 16;
    int hw = pix & 65535;
    int h = hw >> 8, wq = hw & 255;

    const float* awp = aw + i * 9;
    const float* rb = g_r + (size_t)b * HW;
    float alfa = ab[i];
#pragma unroll
    for (int ky = 0; ky < 3; ++ky) {
        int hh = h + ky - 1;
        if ((unsigned)hh >= 256u) continue;
#pragma unroll
        for (int kx = 0; kx < 3; ++kx) {
            int ww = wq + kx - 1;
            if ((unsigned)ww >= 256u) continue;
            alfa += awp[ky * 3 + kx] * rb[hh * 256 + ww];
        }
    }
    float rc = g_r[pix];
    float y = fmaxf(g_ypre[pix] + alfa * rc, 0.f);

    out[OUT_Y + (size_t)i * NPIX + pix] = y;
    g_xc[(b * 3 + 1) * HW + hw] = y;
    if (i == 0) {
        g_xc[(b * 3 + 0) * HW + hw] = fmaxf(x[(b * 7 + 2) * HW + hw], 0.f);
        g_xc[(b * 3 + 2) * HW + hw] = fmaxf(x[(b * 7 + 4) * HW + hw], 0.f);
    }
    if (i == 3) {
        out[(b * 3 + 0) * HW + hw] = g_xc[(b * 3 + 0) * HW + hw];
        out[(b * 3 + 1) * HW + hw] = y;
        out[(b * 3 + 2) * HW + hw] = g_xc[(b * 3 + 2) * HW + hw];
    }
}

// ---------------- launch ----------------
extern "C" void kernel_launch(void* const* d_in, const int* in_sizes, int n_in,
                              void* d_out, int out_size)
{
    const float* x    = (const float*)d_in[0];
    const float* spat = (const float*)d_in[1];
    const float* pw1  = (const float*)d_in[2];
    const float* pb1  = (const float*)d_in[3];
    const float* pw2  = (const float*)d_in[4];
    const float* pb2  = (const float*)d_in[5];
    const float* pw3  = (const float*)d_in[6];
    const float* pb3  = (const float*)d_in[7];
    const float* pw4  = (const float*)d_in[8];
    const float* pb4  = (const float*)d_in[9];
    const float* dw1  = (const float*)d_in[10];
    const float* db1  = (const float*)d_in[11];
    const float* dw2  = (const float*)d_in[12];
    const float* db2  = (const float*)d_in[13];
    const float* rw1  = (const float*)d_in[14];
    const float* rb1  = (const float*)d_in[15];
    const float* rw2  = (const float*)d_in[16];
    const float* rb2  = (const float*)d_in[17];
    const float* aw   = (const float*)d_in[18];
    const float* ab   = (const float*)d_in[19];
    float* out = (float*)d_out;

    cudaFuncSetAttribute(conv32_v7, cudaFuncAttributeMaxDynamicSharedMemorySize, CONV7SM);

    init_xc_kernel<<<1536, 256>>>(x);
    conv1_kernel<<<dim3(256, 7, 2), 256>>>(x, pw1, pb1);
    conv32_v7<<<dim3(64, 7, 8), 256, CONV7SM>>>(0, pw2, pb2);   // h1 -> h2
    conv32_v7<<<dim3(64, 7, 8), 256, CONV7SM>>>(1, pw3, pb3);   // h2 -> h1
    conv4_v4<<<dim3(128, 7, 2), 256>>>(x, pw4, pb4, out + OUT_PRIOR);
    domain_kernel<<<4, 256>>>(spat, dw1, db1, dw2, db2);
    rangek_kernel<<<NPIX / 8, 256>>>(rw1, rb1, rw2, rb2);

    for (int i = 0; i < 4; ++i) {
        bilateral_kernel<<<NPIX / 256, 256>>>(i, x);
        alfa_kernel<<<NPIX / 256, 256>>>(i, x, aw, ab, out);
    }
}